// round 1
// baseline (speedup 1.0000x reference)
#include <cuda_runtime.h>
#include <math.h>

typedef unsigned long long ull;

// ---------------- device globals (scratch; no allocations allowed) ----------
__device__ float  g_sq[8192];     // per-row squared L2 norms of "total"
__device__ float  g_colA[512];    // per-dimension column sums of "total"
__device__ double g_sqsum;        // sum of g_sq in double
__device__ double g_acc[4];       // quadrant sums: [XX, XY, YX, YY] as hi*2+hj
__device__ float  g_coef[5];      // -log2(e)/scale[m]

// ---------------- small helpers --------------------------------------------
__device__ __forceinline__ float ex2f(float x) {
    float y; asm("ex2.approx.ftz.f32 %0, %1;" : "=f"(y) : "f"(x)); return y;
}
__device__ __forceinline__ ull pack2(float a, float b) {
    ull r; asm("mov.b64 %0, {%1, %2};" : "=l"(r) : "f"(a), "f"(b)); return r;
}
__device__ __forceinline__ void unpack2(ull v, float& a, float& b) {
    asm("mov.b64 {%0, %1}, %2;" : "=f"(a), "=f"(b) : "l"(v));
}
__device__ __forceinline__ ull fma2(ull a, ull b, ull c) {
    ull r; asm("fma.rn.f32x2 %0, %1, %2, %3;" : "=l"(r) : "l"(a), "l"(b), "l"(c));
    return r;
}

// ---------------- kernel 0: zero accumulators (graph replays!) --------------
__global__ void k_zero() {
    int t = blockIdx.x * blockDim.x + threadIdx.x;
    if (t < 512) g_colA[t] = 0.f;
    if (t == 0) {
        g_sqsum = 0.0;
        g_acc[0] = g_acc[1] = g_acc[2] = g_acc[3] = 0.0;
    }
}

// ---------------- kernel 1: per-row sq norms + global sqsum -----------------
__global__ void k_sq(const float* __restrict__ src, const float* __restrict__ tgt) {
    int warp = threadIdx.x >> 5, lane = threadIdx.x & 31;
    int row = blockIdx.x * 8 + warp;
    const float* p = (row < 4096) ? src + (size_t)row * 512
                                  : tgt + (size_t)(row - 4096) * 512;
    float s = 0.f;
#pragma unroll
    for (int l = 0; l < 16; l++) { float v = p[lane + l * 32]; s = fmaf(v, v, s); }
#pragma unroll
    for (int o = 16; o; o >>= 1) s += __shfl_xor_sync(0xffffffffu, s, o);
    __shared__ double part[8];
    if (lane == 0) { g_sq[row] = s; part[warp] = (double)s; }
    __syncthreads();
    if (threadIdx.x == 0) {
        double t = 0;
        for (int w = 0; w < 8; w++) t += part[w];
        atomicAdd(&g_sqsum, t);
    }
}

// ---------------- kernel 2: column sums (for closed-form sum(l2)) -----------
__global__ void k_col(const float* __restrict__ src, const float* __restrict__ tgt) {
    int d  = blockIdx.x * 256 + threadIdx.x;          // 0..511
    int r0 = blockIdx.y * 256;                        // 256-row chunk (never straddles halves)
    const float* base = (r0 < 4096) ? src + (size_t)r0 * 512
                                    : tgt + (size_t)(r0 - 4096) * 512;
    float s0 = 0.f, s1 = 0.f, s2 = 0.f, s3 = 0.f;
    for (int i = 0; i < 256; i += 4) {
        s0 += base[(size_t)(i + 0) * 512 + d];
        s1 += base[(size_t)(i + 1) * 512 + d];
        s2 += base[(size_t)(i + 2) * 512 + d];
        s3 += base[(size_t)(i + 3) * 512 + d];
    }
    atomicAdd(&g_colA[d], (s0 + s1) + (s2 + s3));
}

// ---------------- kernel 3: bandwidth -> exp coefficients -------------------
__global__ void k_scale() {
    __shared__ double red[512];
    int t = threadIdx.x;
    double c = (double)g_colA[t];
    red[t] = c * c;
    __syncthreads();
    for (int o = 256; o; o >>= 1) { if (t < o) red[t] += red[t + o]; __syncthreads(); }
    if (t == 0) {
        double n = 8192.0;
        double sum_l2 = 2.0 * n * g_sqsum - 2.0 * red[0];
        double bw = sum_l2 / (n * n - n);
        bw /= 4.0;  // KERNEL_MUL ** (KERNEL_NUM // 2) = 2^2
        const double LOG2E = 1.4426950408889634;
        double s = bw;
        for (int m = 0; m < 5; m++) { g_coef[m] = (float)(-LOG2E / s); s *= 2.0; }
    }
}

// ---------------- kernel 4: fused symmetric GEMM + 5x exp + quadrant sums ---
// Block pairs (bi <= bj) over 64x64 grid of 128x128 tiles; 2080 blocks.
// 256 threads, each computes 8x8 outputs via f32x2 packed FMA.
__global__ __launch_bounds__(256, 2)
void k_mmd(const float* __restrict__ src, const float* __restrict__ tgt) {
    __shared__ __align__(16) float As[16][128];
    __shared__ __align__(16) float Bs[16][128];

    // decode triangular block index: idx = bj*(bj+1)/2 + bi, bi <= bj
    int idx = blockIdx.x;
    int bj = (int)((sqrtf(8.0f * (float)idx + 1.0f) - 1.0f) * 0.5f);
    while ((bj + 1) * (bj + 2) / 2 <= idx) bj++;
    while (bj * (bj + 1) / 2 > idx) bj--;
    int bi = idx - bj * (bj + 1) / 2;

    int rowA = bi * 128, rowB = bj * 128;
    const float* Ab = (rowA < 4096) ? src + (size_t)rowA * 512
                                    : tgt + (size_t)(rowA - 4096) * 512;
    const float* Bb = (rowB < 4096) ? src + (size_t)rowB * 512
                                    : tgt + (size_t)(rowB - 4096) * 512;

    int tid = threadIdx.x;
    int id0 = tid, id1 = tid + 256;
    int ar0 = id0 >> 2, ac0 = (id0 & 3) * 4;   // row / col-offset within 128x16 tile
    int ar1 = id1 >> 2, ac1 = (id1 & 3) * 4;

    // prefetch k-tile 0
    float4 pa0 = *(const float4*)(Ab + (size_t)ar0 * 512 + ac0);
    float4 pa1 = *(const float4*)(Ab + (size_t)ar1 * 512 + ac1);
    float4 pb0 = *(const float4*)(Bb + (size_t)ar0 * 512 + ac0);
    float4 pb1 = *(const float4*)(Bb + (size_t)ar1 * 512 + ac1);

    ull acc[8][4];
#pragma unroll
    for (int i = 0; i < 8; i++)
#pragma unroll
        for (int j = 0; j < 4; j++) acc[i][j] = 0ull;

    int ti = (tid >> 4) * 8;   // i-offset (0..120)
    int tj = (tid & 15) * 8;   // j-offset (0..120)

    for (int kt = 0; kt < 32; kt++) {
        // store prefetched tile to smem, transposed to [k][row]
        As[ac0 + 0][ar0] = pa0.x; As[ac0 + 1][ar0] = pa0.y;
        As[ac0 + 2][ar0] = pa0.z; As[ac0 + 3][ar0] = pa0.w;
        As[ac1 + 0][ar1] = pa1.x; As[ac1 + 1][ar1] = pa1.y;
        As[ac1 + 2][ar1] = pa1.z; As[ac1 + 3][ar1] = pa1.w;
        Bs[ac0 + 0][ar0] = pb0.x; Bs[ac0 + 1][ar0] = pb0.y;
        Bs[ac0 + 2][ar0] = pb0.z; Bs[ac0 + 3][ar0] = pb0.w;
        Bs[ac1 + 0][ar1] = pb1.x; Bs[ac1 + 1][ar1] = pb1.y;
        Bs[ac1 + 2][ar1] = pb1.z; Bs[ac1 + 3][ar1] = pb1.w;
        __syncthreads();

        if (kt < 31) {  // prefetch next tile while computing this one
            int kof = (kt + 1) * 16;
            pa0 = *(const float4*)(Ab + (size_t)ar0 * 512 + kof + ac0);
            pa1 = *(const float4*)(Ab + (size_t)ar1 * 512 + kof + ac1);
            pb0 = *(const float4*)(Bb + (size_t)ar0 * 512 + kof + ac0);
            pb1 = *(const float4*)(Bb + (size_t)ar1 * 512 + kof + ac1);
        }

#pragma unroll
        for (int k = 0; k < 16; k++) {
            float4 a0 = *(const float4*)&As[k][ti];
            float4 a1 = *(const float4*)&As[k][ti + 4];
            ulonglong2 b01 = *(const ulonglong2*)&Bs[k][tj];
            ulonglong2 b23 = *(const ulonglong2*)&Bs[k][tj + 4];
            ull bb0 = b01.x, bb1 = b01.y, bb2 = b23.x, bb3 = b23.y;
            ull a2[8];
            a2[0] = pack2(a0.x, a0.x); a2[1] = pack2(a0.y, a0.y);
            a2[2] = pack2(a0.z, a0.z); a2[3] = pack2(a0.w, a0.w);
            a2[4] = pack2(a1.x, a1.x); a2[5] = pack2(a1.y, a1.y);
            a2[6] = pack2(a1.z, a1.z); a2[7] = pack2(a1.w, a1.w);
#pragma unroll
            for (int i = 0; i < 8; i++) {
                acc[i][0] = fma2(a2[i], bb0, acc[i][0]);
                acc[i][1] = fma2(a2[i], bb1, acc[i][1]);
                acc[i][2] = fma2(a2[i], bb2, acc[i][2]);
                acc[i][3] = fma2(a2[i], bb3, acc[i][3]);
            }
        }
        __syncthreads();
    }

    // ---- epilogue: l2 -> sum of 5 gaussians, accumulate in double ----
    float c0 = g_coef[0], c1 = g_coef[1], c2 = g_coef[2], c3 = g_coef[3], c4 = g_coef[4];
    float sqi[8], sqj[8];
#pragma unroll
    for (int i = 0; i < 8; i++) sqi[i] = g_sq[rowA + ti + i];
#pragma unroll
    for (int j = 0; j < 8; j++) sqj[j] = g_sq[rowB + tj + j];

    double local = 0.0;
#pragma unroll
    for (int i = 0; i < 8; i++) {
#pragma unroll
        for (int jp = 0; jp < 4; jp++) {
            float d0, d1;
            unpack2(acc[i][jp], d0, d1);
            float base0 = sqi[i] + sqj[2 * jp];
            float base1 = sqi[i] + sqj[2 * jp + 1];
            float l0 = fmaxf(fmaf(-2.f, d0, base0), 0.f);
            float l1 = fmaxf(fmaf(-2.f, d1, base1), 0.f);
            float s0 = ex2f(l0 * c0) + ex2f(l0 * c1) + ex2f(l0 * c2)
                     + ex2f(l0 * c3) + ex2f(l0 * c4);
            float s1 = ex2f(l1 * c0) + ex2f(l1 * c1) + ex2f(l1 * c2)
                     + ex2f(l1 * c3) + ex2f(l1 * c4);
            local += (double)(s0 + s1);
        }
    }

    // block-reduce (reuse As as double scratch: 2KB needed, 8KB available)
    __syncthreads();
    double* red = (double*)&As[0][0];
    red[tid] = local;
    __syncthreads();
    for (int o = 128; o; o >>= 1) { if (tid < o) red[tid] += red[tid + o]; __syncthreads(); }
    if (tid == 0) {
        int hi = (bi >= 32), hj = (bj >= 32);
        atomicAdd(&g_acc[hi * 2 + hj], red[0]);
        if (bi != bj) atomicAdd(&g_acc[hj * 2 + hi], red[0]);  // symmetric mirror
    }
}

// ---------------- kernel 5: final scalar ------------------------------------
__global__ void k_final(float* __restrict__ out) {
    double inv = 1.0 / (4096.0 * 4096.0);
    out[0] = (float)((g_acc[0] + g_acc[3] - g_acc[1] - g_acc[2]) * inv);
}

// ---------------- launcher ---------------------------------------------------
extern "C" void kernel_launch(void* const* d_in, const int* in_sizes, int n_in,
                              void* d_out, int out_size) {
    const float* src = (const float*)d_in[0];
    const float* tgt = (const float*)d_in[1];
    float* out = (float*)d_out;

    k_zero<<<2, 256>>>();
    k_sq<<<1024, 256>>>(src, tgt);
    k_col<<<dim3(2, 32), 256>>>(src, tgt);
    k_scale<<<1, 512>>>();
    k_mmd<<<2080, 256>>>(src, tgt);
    k_final<<<1, 1>>>(out);
}

// round 3
// speedup vs baseline: 4.8155x; 4.8155x over previous
#include <cuda_runtime.h>
#include <cuda_bf16.h>
#include <math.h>
#include <stdint.h>

typedef unsigned long long ull;

// ---------------- device globals (scratch; no allocations allowed) ----------
__device__ __nv_bfloat16 g_data[8192 * 512]; // bf16 concatenated [source; target]
__device__ float  g_sq[8192];     // per-row squared L2 norms (fp32, from originals)
__device__ float  g_colA[512];    // per-dimension column sums
__device__ double g_sqsum;        // sum of g_sq in double
__device__ double g_acc[4];       // quadrant sums: [XX, XY, YX, YY] as hi*2+hj
__device__ float  g_cc;           // -log2(e) / (bw * 16)  (largest scale)

// ---------------- PTX helpers ----------------------------------------------
__device__ __forceinline__ float ex2f(float x) {
    float y; asm("ex2.approx.ftz.f32 %0, %1;" : "=f"(y) : "f"(x)); return y;
}
__device__ __forceinline__ uint32_t smem_u32(const void* p) {
    uint32_t a;
    asm("{ .reg .u64 t; cvta.to.shared.u64 t, %1; cvt.u32.u64 %0, t; }" : "=r"(a) : "l"(p));
    return a;
}
__device__ __forceinline__ void cp_async16(uint32_t saddr, const void* g) {
    asm volatile("cp.async.cg.shared.global [%0], [%1], 16;" :: "r"(saddr), "l"(g));
}
#define CP_COMMIT()  asm volatile("cp.async.commit_group;" ::: "memory")
#define CP_WAIT2()   asm volatile("cp.async.wait_group 2;" ::: "memory")

__device__ __forceinline__ void ldsm4(uint32_t& r0, uint32_t& r1, uint32_t& r2,
                                      uint32_t& r3, uint32_t addr) {
    asm volatile("ldmatrix.sync.aligned.m8n8.x4.shared.b16 {%0,%1,%2,%3}, [%4];"
                 : "=r"(r0), "=r"(r1), "=r"(r2), "=r"(r3) : "r"(addr));
}
__device__ __forceinline__ void hmma(float* d, const uint32_t* a, const uint32_t* b) {
    asm volatile(
        "mma.sync.aligned.m16n8k16.row.col.f32.bf16.bf16.f32 "
        "{%0,%1,%2,%3}, {%4,%5,%6,%7}, {%8,%9}, {%0,%1,%2,%3};"
        : "+f"(d[0]), "+f"(d[1]), "+f"(d[2]), "+f"(d[3])
        : "r"(a[0]), "r"(a[1]), "r"(a[2]), "r"(a[3]), "r"(b[0]), "r"(b[1]));
}

// ---------------- kernel 0: zero accumulators (graph replays!) --------------
__global__ void k_zero() {
    int t = blockIdx.x * blockDim.x + threadIdx.x;
    if (t < 512) g_colA[t] = 0.f;
    if (t == 0) {
        g_sqsum = 0.0;
        g_acc[0] = g_acc[1] = g_acc[2] = g_acc[3] = 0.0;
    }
}

// ---------------- kernel 1: round inputs to bf16 into g_data ----------------
__global__ void k_convert(const float* __restrict__ src, const float* __restrict__ tgt) {
    int i = blockIdx.x * 256 + threadIdx.x;            // float4 index, 0..1048575
    const float4* p = (i < 524288) ? (const float4*)src : (const float4*)tgt;
    int j = (i < 524288) ? i : i - 524288;
    float4 v = p[j];
    uint2 o;
    asm("cvt.rn.bf16x2.f32 %0, %1, %2;" : "=r"(o.x) : "f"(v.y), "f"(v.x));
    asm("cvt.rn.bf16x2.f32 %0, %1, %2;" : "=r"(o.y) : "f"(v.w), "f"(v.z));
    ((uint2*)g_data)[i] = o;
}

// ---------------- kernel 2: per-row sq norms + global sqsum -----------------
__global__ void k_sq(const float* __restrict__ src, const float* __restrict__ tgt) {
    int warp = threadIdx.x >> 5, lane = threadIdx.x & 31;
    int row = blockIdx.x * 8 + warp;
    const float* p = (row < 4096) ? src + (size_t)row * 512
                                  : tgt + (size_t)(row - 4096) * 512;
    float s = 0.f;
#pragma unroll
    for (int l = 0; l < 16; l++) { float v = p[lane + l * 32]; s = fmaf(v, v, s); }
#pragma unroll
    for (int o = 16; o; o >>= 1) s += __shfl_xor_sync(0xffffffffu, s, o);
    __shared__ double part[8];
    if (lane == 0) { g_sq[row] = s; part[warp] = (double)s; }
    __syncthreads();
    if (threadIdx.x == 0) {
        double t = 0;
        for (int w = 0; w < 8; w++) t += part[w];
        atomicAdd(&g_sqsum, t);
    }
}

// ---------------- kernel 3: column sums (closed-form sum(l2)) ---------------
__global__ void k_col(const float* __restrict__ src, const float* __restrict__ tgt) {
    int d  = blockIdx.x * 256 + threadIdx.x;
    int r0 = blockIdx.y * 256;
    const float* base = (r0 < 4096) ? src + (size_t)r0 * 512
                                    : tgt + (size_t)(r0 - 4096) * 512;
    float s0 = 0.f, s1 = 0.f, s2 = 0.f, s3 = 0.f;
    for (int i = 0; i < 256; i += 4) {
        s0 += base[(size_t)(i + 0) * 512 + d];
        s1 += base[(size_t)(i + 1) * 512 + d];
        s2 += base[(size_t)(i + 2) * 512 + d];
        s3 += base[(size_t)(i + 3) * 512 + d];
    }
    atomicAdd(&g_colA[d], (s0 + s1) + (s2 + s3));
}

// ---------------- kernel 4: bandwidth -> single exp coefficient -------------
__global__ void k_scale() {
    __shared__ double red[512];
    int t = threadIdx.x;
    double c = (double)g_colA[t];
    red[t] = c * c;
    __syncthreads();
    for (int o = 256; o; o >>= 1) { if (t < o) red[t] += red[t + o]; __syncthreads(); }
    if (t == 0) {
        double n = 8192.0;
        double sum_l2 = 2.0 * n * g_sqsum - 2.0 * red[0];
        double bw = sum_l2 / (n * n - n);
        bw /= 4.0;  // KERNEL_MUL ** (KERNEL_NUM // 2)
        const double LOG2E = 1.4426950408889634;
        // t = exp(-l2/(bw*16)); sum over 5 scales = t + t^2 + t^4 + t^8 + t^16
        g_cc = (float)(-LOG2E / (bw * 16.0));
    }
}

// ---------------- kernel 5: mma.sync bf16 GEMM + fused epilogue -------------
// 128x128 tile per CTA, triangular over 64x64 blocks -> 2080 CTAs.
// 8 warps (2m x 4n), warp tile 64x32. K=512 in 16 chunks of 32, 4-stage cp.async.
static constexpr int KT = 16;
static constexpr int STAGE_BYTES = 16384;   // A 8KB + B 8KB (128 rows x 64B)
static constexpr int SMEM_TOTAL = 4 * STAGE_BYTES;  // 65536

__global__ __launch_bounds__(256, 2)
void k_mma() {
    extern __shared__ char sm[];
    uint32_t sbase = smem_u32(sm);

    int tid = threadIdx.x;
    int wid = tid >> 5, lane = tid & 31;

    // triangular block decode: idx = bj*(bj+1)/2 + bi, bi <= bj (64 blocks)
    int idx = blockIdx.x;
    int bj = (int)((sqrtf(8.0f * (float)idx + 1.0f) - 1.0f) * 0.5f);
    while ((bj + 1) * (bj + 2) / 2 <= idx) bj++;
    while (bj * (bj + 1) / 2 > idx) bj--;
    int bi = idx - bj * (bj + 1) / 2;
    int rowA = bi * 128, rowB = bj * 128;

    // ---- stage loader: 1024 x 16B per stage, 4 per thread --------------------
    auto load_stage = [&](int kt, int slot) {
#pragma unroll
        for (int i = 0; i < 4; i++) {
            int t = tid + i * 256;
            int op = t >> 9;                 // 0:A 1:B
            int r = (t >> 2) & 127;
            int c16 = t & 3;
            int grow = (op ? rowB : rowA) + r;
            const __nv_bfloat16* gp = g_data + (size_t)grow * 512 + kt * 32 + c16 * 8;
            uint32_t sa = sbase + slot * STAGE_BYTES + op * 8192
                        + r * 64 + ((c16 ^ (r & 3)) << 4);
            cp_async16(sa, gp);
        }
        CP_COMMIT();
    };

    load_stage(0, 0);
    load_stage(1, 1);
    load_stage(2, 2);

    int wm = (wid >> 2) * 64;   // warp m offset (0 or 64)
    int wn = (wid & 3) * 32;    // warp n offset

    // precompute ldmatrix lane row indices
    int mat = lane >> 3, r8 = lane & 7;
    int lrow = (mat & 1) * 8 + r8;   // row within 16-row group
    int lhi  = mat >> 1;             // col16 high bit

    float acc[4][4][4];
#pragma unroll
    for (int a = 0; a < 4; a++)
#pragma unroll
        for (int b = 0; b < 4; b++)
#pragma unroll
            for (int c = 0; c < 4; c++) acc[a][b][c] = 0.f;

    for (int kt = 0; kt < KT; kt++) {
        int slot = kt & 3;
        CP_WAIT2();
        __syncthreads();
        if (kt + 3 < KT) load_stage(kt + 3, (kt + 3) & 3);
        else { CP_COMMIT(); }

        uint32_t Ab = sbase + slot * STAGE_BYTES;
        uint32_t Bb = Ab + 8192;

#pragma unroll
        for (int ks = 0; ks < 2; ks++) {
            uint32_t af[4][4], bf[2][4];
#pragma unroll
            for (int mt = 0; mt < 4; mt++) {
                int m = wm + mt * 16 + lrow;
                int c16 = ks * 2 + lhi;
                ldsm4(af[mt][0], af[mt][1], af[mt][2], af[mt][3],
                      Ab + m * 64 + ((c16 ^ (m & 3)) << 4));
            }
#pragma unroll
            for (int g = 0; g < 2; g++) {
                int n = wn + g * 16 + lrow;
                int c16 = ks * 2 + lhi;
                ldsm4(bf[g][0], bf[g][1], bf[g][2], bf[g][3],
                      Bb + n * 64 + ((c16 ^ (n & 3)) << 4));
            }
#pragma unroll
            for (int mt = 0; mt < 4; mt++) {
#pragma unroll
                for (int nt = 0; nt < 4; nt++) {
                    uint32_t bb[2] = { bf[nt >> 1][nt & 1], bf[nt >> 1][(nt & 1) + 2] };
                    hmma(acc[mt][nt], af[mt], bb);
                }
            }
        }
        __syncthreads();
    }

    // ---- epilogue ------------------------------------------------------------
    // stage sq values into smem (stage area is free now)
    float* s_sq = (float*)sm;          // [0:128)=A rows, [128:256)=B rows
    if (tid < 128) s_sq[tid] = g_sq[rowA + tid];
    else if (tid < 256) s_sq[tid] = g_sq[rowB + tid - 128];
    __syncthreads();

    float cc = g_cc;
    int er = lane >> 2, ec = (lane & 3) * 2;
    double dsum = 0.0;
#pragma unroll
    for (int mt = 0; mt < 4; mt++) {
        float sqi0 = s_sq[wm + mt * 16 + er];
        float sqi1 = s_sq[wm + mt * 16 + er + 8];
#pragma unroll
        for (int nt = 0; nt < 4; nt++) {
            float sqj0 = s_sq[128 + wn + nt * 8 + ec];
            float sqj1 = s_sq[128 + wn + nt * 8 + ec + 1];
            float d0 = acc[mt][nt][0], d1 = acc[mt][nt][1];
            float d2 = acc[mt][nt][2], d3 = acc[mt][nt][3];
            float l0 = fmaxf(fmaf(-2.f, d0, sqi0 + sqj0), 0.f);
            float l1 = fmaxf(fmaf(-2.f, d1, sqi0 + sqj1), 0.f);
            float l2 = fmaxf(fmaf(-2.f, d2, sqi1 + sqj0), 0.f);
            float l3 = fmaxf(fmaf(-2.f, d3, sqi1 + sqj1), 0.f);
            float t0 = ex2f(l0 * cc), t1 = ex2f(l1 * cc);
            float t2 = ex2f(l2 * cc), t3 = ex2f(l3 * cc);
            float fs = 0.f;
            {
                float a2 = t0 * t0, a4 = a2 * a2, a8 = a4 * a4;
                fs += ((t0 + a2) + (a4 + a8)) + a8 * a8;
            }
            {
                float a2 = t1 * t1, a4 = a2 * a2, a8 = a4 * a4;
                fs += ((t1 + a2) + (a4 + a8)) + a8 * a8;
            }
            {
                float a2 = t2 * t2, a4 = a2 * a2, a8 = a4 * a4;
                fs += ((t2 + a2) + (a4 + a8)) + a8 * a8;
            }
            {
                float a2 = t3 * t3, a4 = a2 * a2, a8 = a4 * a4;
                fs += ((t3 + a2) + (a4 + a8)) + a8 * a8;
            }
            dsum += (double)fs;
        }
    }

    // block reduce doubles in smem
    __syncthreads();
    double* red = (double*)sm;
    red[tid] = dsum;
    __syncthreads();
    for (int o = 128; o; o >>= 1) { if (tid < o) red[tid] += red[tid + o]; __syncthreads(); }
    if (tid == 0) {
        int hi = (bi >= 32), hj = (bj >= 32);
        atomicAdd(&g_acc[hi * 2 + hj], red[0]);
        if (bi != bj) atomicAdd(&g_acc[hj * 2 + hi], red[0]);
    }
}

// ---------------- kernel 6: final scalar ------------------------------------
__global__ void k_final(float* __restrict__ out) {
    double inv = 1.0 / (4096.0 * 4096.0);
    out[0] = (float)((g_acc[0] + g_acc[3] - g_acc[1] - g_acc[2]) * inv);
}

// ---------------- launcher ---------------------------------------------------
extern "C" void kernel_launch(void* const* d_in, const int* in_sizes, int n_in,
                              void* d_out, int out_size) {
    const float* src = (const float*)d_in[0];
    const float* tgt = (const float*)d_in[1];
    float* out = (float*)d_out;

    cudaFuncSetAttribute(k_mma, cudaFuncAttributeMaxDynamicSharedMemorySize, SMEM_TOTAL);

    k_zero<<<2, 256>>>();
    k_convert<<<4096, 256>>>(src, tgt);
    k_sq<<<1024, 256>>>(src, tgt);
    k_col<<<dim3(2, 32), 256>>>(src, tgt);
    k_scale<<<1, 512>>>();
    k_mma<<<2080, 256, SMEM_TOTAL>>>();
    k_final<<<1, 1>>>(out);
}

// round 4
// speedup vs baseline: 5.0103x; 1.0405x over previous
#include <cuda_runtime.h>
#include <cuda_bf16.h>
#include <math.h>
#include <stdint.h>

typedef unsigned long long ull;

// ---------------- device globals (scratch; no allocations allowed) ----------
__device__ __nv_bfloat16 g_data[8192 * 512]; // bf16 concatenated [source; target]
__device__ float  g_sq[8192];     // per-row squared L2 norms (fp32, from originals)
__device__ float  g_colA[512];    // per-dimension column sums
__device__ double g_sqsum;        // sum of g_sq in double
__device__ double g_acc[4];       // quadrant sums: [XX, XY, YX, YY] as hi*2+hj
__device__ float  g_cc;           // -log2(e) / (bw * 16)  (largest scale)

// ---------------- PTX helpers ----------------------------------------------
__device__ __forceinline__ float ex2f(float x) {
    float y; asm("ex2.approx.ftz.f32 %0, %1;" : "=f"(y) : "f"(x)); return y;
}
__device__ __forceinline__ uint32_t smem_u32(const void* p) {
    uint32_t a;
    asm("{ .reg .u64 t; cvta.to.shared.u64 t, %1; cvt.u32.u64 %0, t; }" : "=r"(a) : "l"(p));
    return a;
}
__device__ __forceinline__ void cp_async16(uint32_t saddr, const void* g) {
    asm volatile("cp.async.cg.shared.global [%0], [%1], 16;" :: "r"(saddr), "l"(g));
}
#define CP_COMMIT()  asm volatile("cp.async.commit_group;" ::: "memory")
#define CP_WAIT2()   asm volatile("cp.async.wait_group 2;" ::: "memory")

__device__ __forceinline__ void ldsm4(uint32_t& r0, uint32_t& r1, uint32_t& r2,
                                      uint32_t& r3, uint32_t addr) {
    asm volatile("ldmatrix.sync.aligned.m8n8.x4.shared.b16 {%0,%1,%2,%3}, [%4];"
                 : "=r"(r0), "=r"(r1), "=r"(r2), "=r"(r3) : "r"(addr));
}
__device__ __forceinline__ void hmma(float* d, const uint32_t* a, const uint32_t* b) {
    asm volatile(
        "mma.sync.aligned.m16n8k16.row.col.f32.bf16.bf16.f32 "
        "{%0,%1,%2,%3}, {%4,%5,%6,%7}, {%8,%9}, {%0,%1,%2,%3};"
        : "+f"(d[0]), "+f"(d[1]), "+f"(d[2]), "+f"(d[3])
        : "r"(a[0]), "r"(a[1]), "r"(a[2]), "r"(a[3]), "r"(b[0]), "r"(b[1]));
}

// ---------------- kernel 0: zero accumulators (graph replays!) --------------
__global__ void k_zero() {
    int t = blockIdx.x * blockDim.x + threadIdx.x;
    if (t < 512) g_colA[t] = 0.f;
    if (t == 0) {
        g_sqsum = 0.0;
        g_acc[0] = g_acc[1] = g_acc[2] = g_acc[3] = 0.0;
    }
}

// ---------------- kernel 1: fused prep: bf16 convert + row sq + col sums ----
// grid 256 x 256 threads. Each warp handles 4 rows; each lane owns 16 fixed
// columns (lane*4 + c*128 + j), accumulating column sums in registers.
__global__ __launch_bounds__(256)
void k_prep(const float* __restrict__ src, const float* __restrict__ tgt) {
    __shared__ float scol[512];
    __shared__ double ssq[8];
    int tid = threadIdx.x, w = tid >> 5, lane = tid & 31;

    for (int i = tid; i < 512; i += 256) scol[i] = 0.f;

    float colacc[16];
#pragma unroll
    for (int i = 0; i < 16; i++) colacc[i] = 0.f;

    double warp_sq = 0.0;
    __syncthreads();

#pragma unroll
    for (int rr = 0; rr < 4; rr++) {
        int row = blockIdx.x * 32 + w * 4 + rr;
        const float* p = (row < 4096) ? src + (size_t)row * 512
                                      : tgt + (size_t)(row - 4096) * 512;
        float s = 0.f;
#pragma unroll
        for (int c = 0; c < 4; c++) {
            float4 v = *(const float4*)(p + lane * 4 + c * 128);
            uint2 o;
            asm("cvt.rn.bf16x2.f32 %0, %1, %2;" : "=r"(o.x) : "f"(v.y), "f"(v.x));
            asm("cvt.rn.bf16x2.f32 %0, %1, %2;" : "=r"(o.y) : "f"(v.w), "f"(v.z));
            *(uint2*)(g_data + (size_t)row * 512 + lane * 4 + c * 128) = o;
            s = fmaf(v.x, v.x, s); s = fmaf(v.y, v.y, s);
            s = fmaf(v.z, v.z, s); s = fmaf(v.w, v.w, s);
            colacc[c * 4 + 0] += v.x; colacc[c * 4 + 1] += v.y;
            colacc[c * 4 + 2] += v.z; colacc[c * 4 + 3] += v.w;
        }
#pragma unroll
        for (int o = 16; o; o >>= 1) s += __shfl_xor_sync(0xffffffffu, s, o);
        if (lane == 0) { g_sq[row] = s; warp_sq += (double)s; }
    }

    // fold per-lane column accumulators into block-level smem
#pragma unroll
    for (int c = 0; c < 4; c++)
#pragma unroll
        for (int j = 0; j < 4; j++)
            atomicAdd(&scol[lane * 4 + c * 128 + j], colacc[c * 4 + j]);
    if (lane == 0) ssq[w] = warp_sq;
    __syncthreads();

    for (int i = tid; i < 512; i += 256) atomicAdd(&g_colA[i], scol[i]);
    if (tid == 0) {
        double t = 0;
        for (int i = 0; i < 8; i++) t += ssq[i];
        atomicAdd(&g_sqsum, t);
    }
}

// ---------------- kernel 2: bandwidth -> single exp coefficient -------------
__global__ void k_scale() {
    __shared__ double red[512];
    int t = threadIdx.x;
    double c = (double)g_colA[t];
    red[t] = c * c;
    __syncthreads();
    for (int o = 256; o; o >>= 1) { if (t < o) red[t] += red[t + o]; __syncthreads(); }
    if (t == 0) {
        double n = 8192.0;
        double sum_l2 = 2.0 * n * g_sqsum - 2.0 * red[0];
        double bw = sum_l2 / (n * n - n);
        bw /= 4.0;  // KERNEL_MUL ** (KERNEL_NUM // 2)
        const double LOG2E = 1.4426950408889634;
        // t = exp(-l2/(bw*16)); sum over 5 scales = t + t^2 + t^4 + t^8 + t^16
        g_cc = (float)(-LOG2E / (bw * 16.0));
    }
}

// ---------------- kernel 3: mma.sync bf16 GEMM + fused epilogue -------------
// 128x128 tile per CTA, triangular over 64x64 blocks -> 2080 CTAs.
// 8 warps (2m x 4n), warp tile 64x32. K=512 in 16 chunks of 32, 4-stage cp.async.
static constexpr int KT = 16;
static constexpr int STAGE_BYTES = 16384;   // A 8KB + B 8KB (128 rows x 64B)
static constexpr int SMEM_TOTAL = 4 * STAGE_BYTES;  // 65536

__global__ __launch_bounds__(256, 2)
void k_mma() {
    extern __shared__ char sm[];
    uint32_t sbase = smem_u32(sm);

    int tid = threadIdx.x;
    int wid = tid >> 5, lane = tid & 31;

    // triangular block decode: idx = bj*(bj+1)/2 + bi, bi <= bj (64 blocks)
    int idx = blockIdx.x;
    int bj = (int)((sqrtf(8.0f * (float)idx + 1.0f) - 1.0f) * 0.5f);
    while ((bj + 1) * (bj + 2) / 2 <= idx) bj++;
    while (bj * (bj + 1) / 2 > idx) bj--;
    int bi = idx - bj * (bj + 1) / 2;
    int rowA = bi * 128, rowB = bj * 128;

    // ---- stage loader: 1024 x 16B per stage, 4 per thread --------------------
    auto load_stage = [&](int kt, int slot) {
#pragma unroll
        for (int i = 0; i < 4; i++) {
            int t = tid + i * 256;
            int op = t >> 9;                 // 0:A 1:B
            int r = (t >> 2) & 127;
            int c16 = t & 3;
            int grow = (op ? rowB : rowA) + r;
            const __nv_bfloat16* gp = g_data + (size_t)grow * 512 + kt * 32 + c16 * 8;
            uint32_t sa = sbase + slot * STAGE_BYTES + op * 8192
                        + r * 64 + ((c16 ^ (r & 3)) << 4);
            cp_async16(sa, gp);
        }
        CP_COMMIT();
    };

    load_stage(0, 0);
    load_stage(1, 1);
    load_stage(2, 2);

    int wm = (wid >> 2) * 64;   // warp m offset (0 or 64)
    int wn = (wid & 3) * 32;    // warp n offset

    // precompute ldmatrix lane row indices
    int mat = lane >> 3, r8 = lane & 7;
    int lrow = (mat & 1) * 8 + r8;   // row within 16-row group
    int lhi  = mat >> 1;             // col16 high bit

    float acc[4][4][4];
#pragma unroll
    for (int a = 0; a < 4; a++)
#pragma unroll
        for (int b = 0; b < 4; b++)
#pragma unroll
            for (int c = 0; c < 4; c++) acc[a][b][c] = 0.f;

    for (int kt = 0; kt < KT; kt++) {
        int slot = kt & 3;
        CP_WAIT2();
        __syncthreads();
        if (kt + 3 < KT) load_stage(kt + 3, (kt + 3) & 3);
        else { CP_COMMIT(); }

        uint32_t Ab = sbase + slot * STAGE_BYTES;
        uint32_t Bb = Ab + 8192;

#pragma unroll
        for (int ks = 0; ks < 2; ks++) {
            uint32_t af[4][4], bf[2][4];
#pragma unroll
            for (int mt = 0; mt < 4; mt++) {
                int m = wm + mt * 16 + lrow;
                int c16 = ks * 2 + lhi;
                ldsm4(af[mt][0], af[mt][1], af[mt][2], af[mt][3],
                      Ab + m * 64 + ((c16 ^ (m & 3)) << 4));
            }
#pragma unroll
            for (int g = 0; g < 2; g++) {
                int n = wn + g * 16 + lrow;
                int c16 = ks * 2 + lhi;
                ldsm4(bf[g][0], bf[g][1], bf[g][2], bf[g][3],
                      Bb + n * 64 + ((c16 ^ (n & 3)) << 4));
            }
#pragma unroll
            for (int mt = 0; mt < 4; mt++) {
#pragma unroll
                for (int nt = 0; nt < 4; nt++) {
                    uint32_t bb[2] = { bf[nt >> 1][nt & 1], bf[nt >> 1][(nt & 1) + 2] };
                    hmma(acc[mt][nt], af[mt], bb);
                }
            }
        }
        __syncthreads();
    }

    // ---- epilogue ------------------------------------------------------------
    // stage sq values into smem (stage area is free now)
    float* s_sq = (float*)sm;          // [0:128)=A rows, [128:256)=B rows
    if (tid < 128) s_sq[tid] = g_sq[rowA + tid];
    else if (tid < 256) s_sq[tid] = g_sq[rowB + tid - 128];
    __syncthreads();

    float cc = g_cc;
    int er = lane >> 2, ec = (lane & 3) * 2;
    double dsum = 0.0;
#pragma unroll
    for (int mt = 0; mt < 4; mt++) {
        float sqi0 = s_sq[wm + mt * 16 + er];
        float sqi1 = s_sq[wm + mt * 16 + er + 8];
#pragma unroll
        for (int nt = 0; nt < 4; nt++) {
            float sqj0 = s_sq[128 + wn + nt * 8 + ec];
            float sqj1 = s_sq[128 + wn + nt * 8 + ec + 1];
            float d0 = acc[mt][nt][0], d1 = acc[mt][nt][1];
            float d2 = acc[mt][nt][2], d3 = acc[mt][nt][3];
            float l0 = fmaxf(fmaf(-2.f, d0, sqi0 + sqj0), 0.f);
            float l1 = fmaxf(fmaf(-2.f, d1, sqi0 + sqj1), 0.f);
            float l2 = fmaxf(fmaf(-2.f, d2, sqi1 + sqj0), 0.f);
            float l3 = fmaxf(fmaf(-2.f, d3, sqi1 + sqj1), 0.f);
            float t0 = ex2f(l0 * cc), t1 = ex2f(l1 * cc);
            float t2 = ex2f(l2 * cc), t3 = ex2f(l3 * cc);
            float fs = 0.f;
            {
                float a2 = t0 * t0, a4 = a2 * a2, a8 = a4 * a4;
                fs += ((t0 + a2) + (a4 + a8)) + a8 * a8;
            }
            {
                float a2 = t1 * t1, a4 = a2 * a2, a8 = a4 * a4;
                fs += ((t1 + a2) + (a4 + a8)) + a8 * a8;
            }
            {
                float a2 = t2 * t2, a4 = a2 * a2, a8 = a4 * a4;
                fs += ((t2 + a2) + (a4 + a8)) + a8 * a8;
            }
            {
                float a2 = t3 * t3, a4 = a2 * a2, a8 = a4 * a4;
                fs += ((t3 + a2) + (a4 + a8)) + a8 * a8;
            }
            dsum += (double)fs;
        }
    }

    // block reduce doubles in smem
    __syncthreads();
    double* red = (double*)sm;
    red[tid] = dsum;
    __syncthreads();
    for (int o = 128; o; o >>= 1) { if (tid < o) red[tid] += red[tid + o]; __syncthreads(); }
    if (tid == 0) {
        int hi = (bi >= 32), hj = (bj >= 32);
        atomicAdd(&g_acc[hi * 2 + hj], red[0]);
        if (bi != bj) atomicAdd(&g_acc[hj * 2 + hi], red[0]);
    }
}

// ---------------- kernel 4: final scalar ------------------------------------
__global__ void k_final(float* __restrict__ out) {
    double inv = 1.0 / (4096.0 * 4096.0);
    out[0] = (float)((g_acc[0] + g_acc[3] - g_acc[1] - g_acc[2]) * inv);
}

// ---------------- launcher ---------------------------------------------------
extern "C" void kernel_launch(void* const* d_in, const int* in_sizes, int n_in,
                              void* d_out, int out_size) {
    const float* src = (const float*)d_in[0];
    const float* tgt = (const float*)d_in[1];
    float* out = (float*)d_out;

    cudaFuncSetAttribute(k_mma, cudaFuncAttributeMaxDynamicSharedMemorySize, SMEM_TOTAL);

    k_zero<<<2, 256>>>();
    k_prep<<<256, 256>>>(src, tgt);
    k_scale<<<1, 512>>>();
    k_mma<<<2080, 256, SMEM_TOTAL>>>();
    k_final<<<1, 1>>>(out);
}